// round 4
// baseline (speedup 1.0000x reference)
#include <cuda_runtime.h>
#include <cuda_bf16.h>
#include <cstdint>

#define BB 8
#define CC 64
#define NN 100000
#define RR 32
#define R3 32768  // 32^3

// Scratch: sums in [b, v, c] layout so one point's 64 channel-adds are contiguous
// (vectorizable with red.global.add.v4.f32). 64MB, L2-resident during accumulation.
__device__ float g_sums[(size_t)BB * R3 * CC];
__device__ int   g_cnt[BB * R3];

// ---------------------------------------------------------------------------
// Zero the scratch (sums + counts) with float4 stores.
// total float4 slots: 16777216/4 + 262144/4 = 4,194,304 + 65,536 = 4,259,840
__global__ void zero_kernel() {
    const int SUMS4 = (BB * R3 * CC) / 4;   // 4,194,304
    const int CNT4  = (BB * R3) / 4;        // 65,536
    int i = blockIdx.x * blockDim.x + threadIdx.x;
    if (i < SUMS4) {
        reinterpret_cast<float4*>(g_sums)[i] = make_float4(0.f, 0.f, 0.f, 0.f);
    } else if (i < SUMS4 + CNT4) {
        reinterpret_cast<int4*>(g_cnt)[i - SUMS4] = make_int4(0, 0, 0, 0);
    }
}

// ---------------------------------------------------------------------------
// Per-point kernel: compute voxel index, emit coords output, accumulate
// counts + channel sums (vector atomics into [b,v,c] scratch).
// mode: 0 = no coords output, 1 = int64 coords, 2 = float coords
__global__ void point_kernel(const float* __restrict__ feat,
                             const float* __restrict__ coords,
                             char* out_coords, int mode) {
    int n = blockIdx.x * blockDim.x + threadIdx.x;
    int b = blockIdx.y;
    if (n >= NN) return;

    const float* cb = coords + (size_t)b * 3 * NN;
    float x = __ldcs(cb + n);
    float y = __ldcs(cb + NN + n);
    float z = __ldcs(cb + 2 * NN + n);

    // clip(coord*R, 0, R-1) then round-to-nearest-even (matches jnp.round)
    int vx = (int)rintf(fminf(fmaxf(x * 32.f, 0.f), 31.f));
    int vy = (int)rintf(fminf(fmaxf(y * 32.f, 0.f), 31.f));
    int vz = (int)rintf(fminf(fmaxf(z * 32.f, 0.f), 31.f));
    int idx = vx * 1024 + vy * 32 + vz;

    if (mode == 1) {
        long long* oc = reinterpret_cast<long long*>(out_coords) + (size_t)b * 3 * NN;
        oc[n]          = (long long)vx;
        oc[NN + n]     = (long long)vy;
        oc[2 * NN + n] = (long long)vz;
    } else if (mode == 2) {
        float* oc = reinterpret_cast<float*>(out_coords) + (size_t)b * 3 * NN;
        oc[n]          = (float)vx;
        oc[NN + n]     = (float)vy;
        oc[2 * NN + n] = (float)vz;
    }

    int voxel = b * R3 + idx;
    atomicAdd(&g_cnt[voxel], 1);

    float* sbase = &g_sums[(size_t)voxel * CC];
    const float* fb = feat + ((size_t)b * CC) * NN + n;

#pragma unroll
    for (int c = 0; c < CC; c += 4) {
        float f0 = __ldcs(fb + (size_t)(c + 0) * NN);
        float f1 = __ldcs(fb + (size_t)(c + 1) * NN);
        float f2 = __ldcs(fb + (size_t)(c + 2) * NN);
        float f3 = __ldcs(fb + (size_t)(c + 3) * NN);
        asm volatile("red.global.add.v4.f32 [%0], {%1,%2,%3,%4};"
                     :: "l"(sbase + c), "f"(f0), "f"(f1), "f"(f2), "f"(f3)
                     : "memory");
    }
}

// ---------------------------------------------------------------------------
// Transpose [b, v, c] -> [b, c, v] fused with the mean (multiply by 1/max(cnt,1)).
// 64-voxel x 64-channel tiles via padded shared memory; both gmem sides coalesced.
__global__ void transpose_mean_kernel(float* __restrict__ out) {
    __shared__ float tile[64 * 65];  // padded: bank = (v + c) % 32, conflict-free
    __shared__ float rcp[64];

    int b  = blockIdx.y;
    int v0 = blockIdx.x * 64;
    int tid = threadIdx.x;  // 256 threads

    // Load 64 voxels x 64 channels (4096 floats) coalesced as float4
    const float4* src4 = reinterpret_cast<const float4*>(
        &g_sums[((size_t)b * R3 + v0) * CC]);
#pragma unroll
    for (int e4 = tid; e4 < 1024; e4 += 256) {
        float4 vv = src4[e4];
        int lin = e4 * 4;
        int v = lin >> 6;        // /64
        int c = lin & 63;
        tile[v * 65 + c + 0] = vv.x;
        tile[v * 65 + c + 1] = vv.y;
        tile[v * 65 + c + 2] = vv.z;
        tile[v * 65 + c + 3] = vv.w;
    }
    if (tid < 64) {
        int cnt = g_cnt[b * R3 + v0 + tid];
        rcp[tid] = 1.0f / fmaxf((float)cnt, 1.0f);
    }
    __syncthreads();

    // Write transposed: out[b, c, v0+vi], consecutive vi -> coalesced float4
    float* obase = out + (size_t)b * CC * R3 + v0;
#pragma unroll
    for (int q = tid; q < 1024; q += 256) {
        int lin = q * 4;
        int c  = lin >> 6;
        int vi = lin & 63;
        float4 o;
        o.x = tile[(vi + 0) * 65 + c] * rcp[vi + 0];
        o.y = tile[(vi + 1) * 65 + c] * rcp[vi + 1];
        o.z = tile[(vi + 2) * 65 + c] * rcp[vi + 2];
        o.w = tile[(vi + 3) * 65 + c] * rcp[vi + 3];
        *reinterpret_cast<float4*>(obase + (size_t)c * R3 + vi) = o;
    }
}

// ---------------------------------------------------------------------------
extern "C" void kernel_launch(void* const* d_in, const int* in_sizes, int n_in,
                              void* d_out, int out_size) {
    const float* feat   = (const float*)d_in[0];  // [B, C, N] f32
    const float* coords = (const float*)d_in[1];  // [B, 3, N] f32

    const int FEAT_ELEMS  = BB * CC * R3;   // 16,777,216
    const int COORD_ELEMS = BB * 3 * NN;    // 2,400,000

    // Decide how the second output (int64 vox_coords) is packed into d_out.
    int mode;
    if (out_size >= FEAT_ELEMS + 2 * COORD_ELEMS) {
        mode = 1;  // int64 bytes after the f32 feat block
    } else if (out_size >= FEAT_ELEMS + COORD_ELEMS) {
        mode = 2;  // coords cast to f32
    } else {
        mode = 0;  // feat only
    }
    char* out_coords = (char*)d_out + (size_t)FEAT_ELEMS * sizeof(float);

    // 1) zero scratch
    {
        const int total4 = (BB * R3 * CC) / 4 + (BB * R3) / 4;  // 4,259,840
        int blocks = (total4 + 255) / 256;
        zero_kernel<<<blocks, 256>>>();
    }
    // 2) scatter-accumulate per point
    {
        dim3 grid((NN + 255) / 256, BB);
        point_kernel<<<grid, 256>>>(feat, coords, out_coords, mode);
    }
    // 3) transpose + mean into d_out
    {
        dim3 grid(R3 / 64, BB);
        transpose_mean_kernel<<<grid, 256>>>((float*)d_out);
    }
}